// round 10
// baseline (speedup 1.0000x reference)
#include <cuda_runtime.h>
#include <cuda_bf16.h>
#include <cstdint>
#include <cstddef>

#define DD      512
#define TSTEPS  256
#define BDIM    256
#define ZROWS   32768          // slices 0..127 kept as bf16 A-source

typedef unsigned short ushort_t;

// ---------------- static device storage (no allocs) ----------------
__device__ ushort_t g_zh[ZROWS * DD];        // z slices bf16 hi
__device__ ushort_t g_zl[ZROWS * DD];        // z slices bf16 lo
__device__ ushort_t g_z0h[BDIM * DD], g_z0l[BDIM * DD];
__device__ ushort_t g_pwh[8][DD * DD], g_pwl[8][DD * DD];    // K^(2^j) bf16
__device__ ushort_t g_pwth[8][DD * DD], g_pwtl[8][DD * DD];  // transposed [n][k]
__device__ unsigned int g_bar[16];           // monotonic level barriers

// ---------------- helpers ----------------
__device__ __forceinline__ uint32_t smem_u32(const void* p) {
    uint32_t a;
    asm("{ .reg .u64 t; cvta.to.shared.u64 t, %1; cvt.u32.u64 %0, t; }"
        : "=r"(a) : "l"(p));
    return a;
}

#define CP16(dst, src) \
    asm volatile("cp.async.cg.shared.global [%0], [%1], 16;" \
                 :: "r"(dst), "l"(src) : "memory")
#define CP_COMMIT() asm volatile("cp.async.commit_group;" ::: "memory")
#define CP_WAIT0()  asm volatile("cp.async.wait_group 0;" ::: "memory")
#define CP_WAIT1()  asm volatile("cp.async.wait_group 1;" ::: "memory")

#define LDSM4(R, a) \
    asm volatile("ldmatrix.sync.aligned.m8n8.x4.shared.b16 {%0,%1,%2,%3},[%4];" \
                 : "=r"((R)[0]), "=r"((R)[1]), "=r"((R)[2]), "=r"((R)[3]) : "r"(a))

#define MMA(C, A, b0v, b1v) \
    asm volatile("mma.sync.aligned.m16n8k16.row.col.f32.bf16.bf16.f32 " \
                 "{%0,%1,%2,%3},{%4,%5,%6,%7},{%8,%9},{%0,%1,%2,%3};" \
                 : "+f"((C)[0]), "+f"((C)[1]), "+f"((C)[2]), "+f"((C)[3]) \
                 : "r"((A)[0]), "r"((A)[1]), "r"((A)[2]), "r"((A)[3]), \
                   "r"(b0v), "r"(b1v))

__device__ __forceinline__ void split_bf16(float f, ushort_t& h, ushort_t& l) {
    __nv_bfloat16 bh = __float2bfloat16_rn(f);
    float fl = f - __bfloat162float(bh);
    __nv_bfloat16 bl = __float2bfloat16_rn(fl);
    h = *reinterpret_cast<ushort_t*>(&bh);
    l = *reinterpret_cast<ushort_t*>(&bl);
}

// ---------------- prep: K -> pw0 / pwT0 bf16 ; z0 -> z0 bf16 ----------------
__global__ void prep_kernel(const float* __restrict__ K, const float* __restrict__ z0)
{
    const int r = blockIdx.x;
    if (r < DD) {
        for (int c = threadIdx.x; c < DD; c += blockDim.x) {
            ushort_t h, l; split_bf16(K[r * DD + c], h, l);
            g_pwh[0][r * DD + c] = h;  g_pwl[0][r * DD + c] = l;
            g_pwth[0][c * DD + r] = h; g_pwtl[0][c * DD + r] = l;
        }
    } else {
        const int rr = r - DD;
        for (int c = threadIdx.x; c < DD; c += blockDim.x) {
            ushort_t h, l; split_bf16(z0[rr * DD + c], h, l);
            g_z0h[rr * DD + c] = h;  g_z0l[rr * DD + c] = l;
        }
    }
}

// ---------------- GEMM tile: 64 x 128, KC=64, 8 chunks, 3-term split --------
#define KC      64
#define CHUNKS  8
#define PLANE_A 8192
#define PLANE_B 16384
#define STAGE   49152

#define LOAD_CHUNK(chv, sv) do {                                               \
    const int kbase_ = (chv) * KC;                                             \
    _Pragma("unroll")                                                          \
    for (int p_ = 0; p_ < 2; ++p_) {                                           \
        const ushort_t* sp_ = srcs[p_];                                        \
        _Pragma("unroll")                                                      \
        for (int rep_ = 0; rep_ < 2; ++rep_) {                                 \
            const int c_   = tid + rep_ * 256;                                 \
            const int row_ = c_ >> 3;                                          \
            const int cc_  = (c_ & 7) * 8;                                     \
            const uint32_t dst_ = sbu + (uint32_t)(sv) * STAGE                 \
                + (uint32_t)p_ * PLANE_A + (uint32_t)(row_ * 128)              \
                + (((uint32_t)(cc_ * 2)) ^ ((uint32_t)(row_ & 7) << 4));       \
            CP16(dst_, sp_ + (size_t)row_ * DD + kbase_ + cc_);                \
        }                                                                      \
    }                                                                          \
    _Pragma("unroll")                                                          \
    for (int p_ = 0; p_ < 2; ++p_) {                                           \
        const ushort_t* sp_ = srcs[2 + p_];                                    \
        _Pragma("unroll")                                                      \
        for (int rep_ = 0; rep_ < 4; ++rep_) {                                 \
            const int c_   = tid + rep_ * 256;                                 \
            const int row_ = c_ >> 3;                                          \
            const int cc_  = (c_ & 7) * 8;                                     \
            const uint32_t dst_ = sbu + (uint32_t)(sv) * STAGE                 \
                + 2 * PLANE_A + (uint32_t)p_ * PLANE_B + (uint32_t)(row_ * 128)\
                + (((uint32_t)(cc_ * 2)) ^ ((uint32_t)(row_ & 7) << 4));       \
            CP16(dst_, sp_ + (size_t)row_ * DD + kbase_ + cc_);                \
        }                                                                      \
    }                                                                          \
} while (0)

struct LvlPtrs {
    const ushort_t *a1h, *a1l, *a2h, *a2l, *bh, *bl;
    ushort_t *nH, *nL, *nTH, *nTL;
    int M1, tofs, dstOfs;
};

__device__ __forceinline__ void gemm_tile(
    char* sb, uint32_t sbu, int tid, int wid, int lane,
    int rowBlk, int n0, const LvlPtrs& L, float* __restrict__ outF)
{
    const int wm = wid & 1;
    const int wn = wid >> 1;

    const bool inA1 = (rowBlk < L.M1);
    const ushort_t* srcs[4];
    const size_t aOfs = (size_t)(inA1 ? rowBlk : (rowBlk - L.M1)) * DD;
    srcs[0] = (inA1 ? L.a1h : L.a2h) + aOfs;
    srcs[1] = (inA1 ? L.a1l : L.a2l) + aOfs;
    srcs[2] = L.bh + (size_t)n0 * DD;
    srcs[3] = L.bl + (size_t)n0 * DD;

    uint32_t aOff[2], aXor[2];
    {
        const int r0 = wm * 32 + (lane & 15);
        #pragma unroll
        for (int mt = 0; mt < 2; ++mt) {
            const int r = r0 + mt * 16;
            aOff[mt] = (uint32_t)(r * 128);
            aXor[mt] = (uint32_t)((r & 7) << 4);
        }
    }
    const uint32_t aColB = (uint32_t)((lane >> 4) * 16);
    uint32_t bOff[2], bXor[2];
    {
        const int r0 = wn * 32 + (lane & 7) + 8 * (lane >> 4);
        #pragma unroll
        for (int np = 0; np < 2; ++np) {
            const int r = r0 + np * 16;
            bOff[np] = (uint32_t)(r * 128);
            bXor[np] = (uint32_t)((r & 7) << 4);
        }
    }
    const uint32_t bColB = (uint32_t)(((lane >> 3) & 1) * 16);

    float acc[2][4][4];
    #pragma unroll
    for (int mt = 0; mt < 2; ++mt)
        #pragma unroll
        for (int nt = 0; nt < 4; ++nt)
            #pragma unroll
            for (int q = 0; q < 4; ++q) acc[mt][nt][q] = 0.f;

    LOAD_CHUNK(0, 0); CP_COMMIT();

    for (int ch = 0; ch < CHUNKS; ++ch) {
        if (ch + 1 < CHUNKS) { LOAD_CHUNK(ch + 1, (ch + 1) & 1); CP_COMMIT(); CP_WAIT1(); }
        else                 { CP_WAIT0(); }
        __syncthreads();

        const uint32_t base = sbu + (uint32_t)(ch & 1) * STAGE;
        #pragma unroll
        for (int k16 = 0; k16 < 4; ++k16) {
            const uint32_t cA = (uint32_t)(k16 * 32) + aColB;
            const uint32_t cB = (uint32_t)(k16 * 32) + bColB;
            uint32_t ah[2][4], al[2][4], bhf[2][4], blf[2][4];
            #pragma unroll
            for (int mt = 0; mt < 2; ++mt) {
                LDSM4(ah[mt], base + 0 * PLANE_A + aOff[mt] + (cA ^ aXor[mt]));
                LDSM4(al[mt], base + 1 * PLANE_A + aOff[mt] + (cA ^ aXor[mt]));
            }
            #pragma unroll
            for (int np = 0; np < 2; ++np) {
                LDSM4(bhf[np], base + 2 * PLANE_A + 0 * PLANE_B + bOff[np] + (cB ^ bXor[np]));
                LDSM4(blf[np], base + 2 * PLANE_A + 1 * PLANE_B + bOff[np] + (cB ^ bXor[np]));
            }
            #pragma unroll
            for (int mt = 0; mt < 2; ++mt)
                #pragma unroll
                for (int nt = 0; nt < 4; ++nt) {
                    const uint32_t* bp = &bhf[nt >> 1][(nt & 1) * 2];
                    MMA(acc[mt][nt], ah[mt], bp[0], bp[1]);
                }
            #pragma unroll
            for (int mt = 0; mt < 2; ++mt)
                #pragma unroll
                for (int nt = 0; nt < 4; ++nt) {
                    const uint32_t* lp = &blf[nt >> 1][(nt & 1) * 2];
                    MMA(acc[mt][nt], ah[mt], lp[0], lp[1]);
                }
            #pragma unroll
            for (int mt = 0; mt < 2; ++mt)
                #pragma unroll
                for (int nt = 0; nt < 4; ++nt) {
                    const uint32_t* bp = &bhf[nt >> 1][(nt & 1) * 2];
                    MMA(acc[mt][nt], al[mt], bp[0], bp[1]);
                }
        }
        __syncthreads();
    }

    // epilogue
    #pragma unroll
    for (int mt = 0; mt < 2; ++mt)
        #pragma unroll
        for (int nt = 0; nt < 4; ++nt) {
            const int rbase = rowBlk + wm * 32 + mt * 16 + (lane >> 2);
            const int col   = n0 + wn * 32 + nt * 8 + 2 * (lane & 3);
            #pragma unroll
            for (int half = 0; half < 2; ++half) {
                const int g = rbase + half * 8;
                const float c0 = acc[mt][nt][half * 2];
                const float c1 = acc[mt][nt][half * 2 + 1];
                ushort_t h0, l0, h1, l1;
                split_bf16(c0, h0, l0); split_bf16(c1, h1, l1);
                const uint32_t ph = (uint32_t)h0 | ((uint32_t)h1 << 16);
                const uint32_t pl = (uint32_t)l0 | ((uint32_t)l1 << 16);
                if (inA1) {
                    float2 v; v.x = c0; v.y = c1;
                    *reinterpret_cast<float2*>(
                        outF + ((size_t)(g & 255) * TSTEPS + (size_t)L.tofs + (g >> 8)) * DD
                             + col) = v;
                    const int zr = g + L.dstOfs;
                    if (zr < ZROWS) {
                        *reinterpret_cast<uint32_t*>(g_zh + (size_t)zr * DD + col) = ph;
                        *reinterpret_cast<uint32_t*>(g_zl + (size_t)zr * DD + col) = pl;
                    }
                } else {
                    const int r = g - L.M1;
                    const size_t o = (size_t)r * DD + col;
                    *reinterpret_cast<uint32_t*>(L.nH + o) = ph;
                    *reinterpret_cast<uint32_t*>(L.nL + o) = pl;
                    L.nTH[(size_t)col * DD + r]       = h0;
                    L.nTH[(size_t)(col + 1) * DD + r] = h1;
                    L.nTL[(size_t)col * DD + r]       = l0;
                    L.nTL[(size_t)(col + 1) * DD + r] = l1;
                }
            }
        }
}

// ---------------- persistent kernel: all 9 levels + global barriers ---------
__global__ void __launch_bounds__(256, 2)
persist_kernel(float* __restrict__ outF, int G)
{
    extern __shared__ char dsm[];
    char* sb = (char*)(((uintptr_t)dsm + 1023) & ~(uintptr_t)1023);
    const uint32_t sbu = smem_u32(sb);
    const int tid  = threadIdx.x;
    const int wid  = tid >> 5;
    const int lane = tid & 31;

    for (int lvl = 0; lvl < 9; ++lvl) {
        LvlPtrs L;
        int rowsTot;
        if (lvl == 0) {
            L.a1h = g_z0h; L.a1l = g_z0l; L.a2h = g_z0h; L.a2l = g_z0l;
            L.bh = g_pwth[0]; L.bl = g_pwtl[0];
            L.nH = g_pwh[0]; L.nL = g_pwl[0]; L.nTH = g_pwth[0]; L.nTL = g_pwtl[0];
            L.M1 = BDIM; rowsTot = BDIM; L.tofs = 0; L.dstOfs = 0;
        } else {
            const int j = lvl - 1;
            L.M1 = BDIM << j; rowsTot = L.M1 + ((j < 7) ? DD : 0);
            L.tofs = 1 << j; L.dstOfs = L.M1;
            L.a1h = g_zh; L.a1l = g_zl;
            L.a2h = g_pwh[j]; L.a2l = g_pwl[j];
            L.bh = g_pwth[j]; L.bl = g_pwtl[j];
            const int jn = (j < 7) ? j + 1 : 7;
            L.nH = g_pwh[jn]; L.nL = g_pwl[jn];
            L.nTH = g_pwth[jn]; L.nTL = g_pwtl[jn];
        }
        const int tiles = (rowsTot >> 6) * 4;

        for (int t = blockIdx.x; t < tiles; t += G) {
            const int rowBlk = (t >> 2) * 64;
            const int n0     = (t & 3) * 128;
            gemm_tile(sb, sbu, tid, wid, lane, rowBlk, n0, L, outF);
        }

        if (lvl < 8) {
            __threadfence();
            __syncthreads();
            if (tid == 0) {
                const unsigned int old = atomicAdd(&g_bar[lvl], 1u);
                const unsigned int target = (old / (unsigned)G + 1u) * (unsigned)G;
                unsigned int cur;
                do {
                    asm volatile("ld.acquire.gpu.u32 %0,[%1];"
                                 : "=r"(cur) : "l"(&g_bar[lvl]) : "memory");
                } while (cur < target);
            }
            __syncthreads();
        }
    }
}

// ---------------- host ----------------
extern "C" void kernel_launch(void* const* d_in, const int* in_sizes, int n_in,
                              void* d_out, int out_size)
{
    const float* z0 = (const float*)d_in[0];
    const float* K  = (const float*)d_in[1];
    float* out = (float*)d_out;

    const int SMEM = 2 * STAGE + 1024;   // 99328 B
    static int G = 0;                    // deterministic; computed once
    if (G == 0) {
        cudaFuncSetAttribute(persist_kernel,
                             cudaFuncAttributeMaxDynamicSharedMemorySize, SMEM);
        int dev = 0, sms = 0, bpm = 0;
        cudaGetDevice(&dev);
        cudaDeviceGetAttribute(&sms, cudaDevAttrMultiProcessorCount, dev);
        cudaOccupancyMaxActiveBlocksPerMultiprocessor(&bpm, persist_kernel, 256, SMEM);
        if (bpm < 1) bpm = 1;
        if (bpm > 2) bpm = 2;
        if (sms < 1) sms = 1;
        G = sms * bpm;
    }

    prep_kernel<<<DD + BDIM, 256>>>(K, z0);
    persist_kernel<<<G, 256, SMEM>>>(out, G);
}